// round 15
// baseline (speedup 1.0000x reference)
#include <cuda_runtime.h>
#include <math.h>

#define Bn 32
#define Tn 64
#define In 300
#define Hn 168
#define Cn 168
#define Sn 512
#define Vn 50257
#define ICn (In + Cn)      // 468
#define NCH 4
#define SCH (Sn / NCH)     // 128
#define HHALF 84           // h-split for the attention tanh phase

// ---------------- device scratch (static, no allocation) ----------------
__device__ float g_spT[Bn * Hn * Sn];       // seq_proj transposed [b][h][s]
__device__ float g_xT[Tn * In * Bn];        // x transposed [t][k][b]
__device__ float g_c[Bn * Hn];              // LSTM cell state [b][j]
__device__ float g_psum[Bn * NCH];          // softmax partial sums
__device__ float g_pctx[NCH * Cn * Bn];     // ctx partials [ch][c][b]  (b fastest)
__device__ __align__(16) float g_Hall[Bn * Tn * Hn];  // hidden states row-major (float4-read)
__device__ float g_HT[Tn * Hn * Bn];        // hidden states [t][j][b]  (for recurrence)

// ---------------- fast-accurate activations (MUFU EX2/RCP, ~1e-6 rel) ----
__device__ __forceinline__ float fsig(float x) {
    return __fdividef(1.f, 1.f + __expf(-x));
}
__device__ __forceinline__ float ftanh(float x) {
    return 1.f - __fdividef(2.f, __expf(2.f * x) + 1.f);
}

// ---------------- f32x2 packed math helpers -----------------------------
__device__ __forceinline__ unsigned long long dup2(float a) {
    unsigned long long d;
    asm("mov.b64 %0, {%1, %1};" : "=l"(d) : "f"(a));
    return d;
}
__device__ __forceinline__ unsigned long long ffma2(unsigned long long a,
                                                    unsigned long long b,
                                                    unsigned long long c) {
    unsigned long long d;
    asm("fma.rn.f32x2 %0, %1, %2, %3;" : "=l"(d) : "l"(a), "l"(b), "l"(c));
    return d;
}
__device__ __forceinline__ void unpack2(unsigned long long v, float& lo, float& hi) {
    asm("mov.b64 {%0, %1}, %2;" : "=f"(lo), "=f"(hi) : "l"(v));
}

// ---------------- transpose x -> xT[t][k][b]; also zero cell state -------
__global__ void __launch_bounds__(256) k_xT(const float* __restrict__ x) {
    int i = blockIdx.x * blockDim.x + threadIdx.x;
    if (i < Tn * In * Bn) {
        int b = i % Bn;
        int k = (i / Bn) % In;
        int t = i / (Bn * In);
        g_xT[i] = x[(b * Tn + t) * In + k];
    }
    if (i < Bn * Hn) g_c[i] = 0.f;  // fold init: grid >> Bn*Hn
}

// ---------------- seq_proj: spT[b][h][s] = sum_c context[b][s][c]*Ws[c][h]
__global__ void __launch_bounds__(256) k_seqproj(const float* __restrict__ context,
                                                 const float* __restrict__ att_Ws) {
    __shared__ float cs[64 * 169];  // padded stride 169 (odd -> conflict-free)
    int b = blockIdx.y;
    int s0 = blockIdx.x * 64;
    for (int idx = threadIdx.x; idx < 64 * Cn; idx += 256) {
        int sl = idx / Cn, c = idx % Cn;
        cs[sl * 169 + c] = context[(b * Sn + s0 + sl) * Cn + c];
    }
    __syncthreads();
    for (int oi = threadIdx.x; oi < Hn * 64; oi += 256) {
        int h = oi / 64, sl = oi % 64;
        float a0 = 0.f, a1 = 0.f;  // 2 accumulators: break RAW chain
        const float* wp = att_Ws + h;
        const float* cp = cs + sl * 169;
#pragma unroll 4
        for (int c = 0; c < Cn; c += 2) {
            a0 = fmaf(cp[c], wp[c * Hn], a0);
            a1 = fmaf(cp[c + 1], wp[(c + 1) * Hn], a1);
        }
        g_spT[(b * Hn + h) * Sn + s0 + sl] = a0 + a1;
    }
}

// ---------------- attention (one step): partial softmax + partial ctx ----
// 256 threads: tanh phase uses 2 threads per s (h split 84/84) to halve the
// per-warp MUFU serial chain. Fully-masked chunks skip the z phase entirely.
__global__ void __launch_bounds__(256) k_attn(const float* __restrict__ context,
                                              const int* __restrict__ clen,
                                              const float* __restrict__ att_Wx,
                                              const float* __restrict__ att_b,
                                              const float* __restrict__ att_v,
                                              int t) {
    __shared__ float z[Hn], hs[Hn], av[Hn], p[SCH], pe2[2][SCH], wsum[4];
    int b = blockIdx.y, ch = blockIdx.x;
    int tid = threadIdx.x;

    int len = clen[b];
    bool active = (ch * SCH) < len;  // any unmasked position in this chunk?
    // NOTE: 'active' is block-uniform (depends on blockIdx only), so the
    // __syncthreads() inside the branch are safe.

    if (active) {
        if (tid < Hn) {
            hs[tid] = (t == 0) ? 0.f : g_HT[((t - 1) * Hn + tid) * Bn + b];
            av[tid] = att_v[tid];
        }
        __syncthreads();
        if (tid < Hn) {
            float a0 = att_b[tid], a1 = 0.f;
#pragma unroll 4
            for (int j = 0; j < Hn; j += 2) {
                a0 = fmaf(hs[j], att_Wx[j * Hn + tid], a0);
                a1 = fmaf(hs[j + 1], att_Wx[(j + 1) * Hn + tid], a1);
            }
            z[tid] = a0 + a1;
        }
        __syncthreads();

        {   // tanh phase: 2 threads per s, each covers 84 h-values
            int sl = tid & (SCH - 1);
            int half = tid >> 7;           // 0 or 1
            int s = ch * SCH + sl;
            float e = 0.f;
            if (s < len) {
                const float* sp = g_spT + b * Hn * Sn + s;
                int h0 = half * HHALF;
#pragma unroll 4
                for (int h = h0; h < h0 + HHALF; ++h) {
                    float u = z[h] + sp[h * Sn];
                    e = fmaf(av[h], ftanh(u), e);
                }
            }
            pe2[half][sl] = e;
        }
        __syncthreads();
    }

    if (tid < SCH) {
        int s = ch * SCH + tid;
        // |e| <= sum|att_v| ~ 6.7 -> exp never overflows; masked -> 0
        float pe = (active && s < len) ? __expf(pe2[0][tid] + pe2[1][tid]) : 0.f;
        p[tid] = pe;
        float r = pe;
#pragma unroll
        for (int off = 16; off; off >>= 1) r += __shfl_down_sync(0xffffffffu, r, off);
        if ((tid & 31) == 0) wsum[tid >> 5] = r;
    }
    __syncthreads();
    if (tid == 0) g_psum[b * NCH + ch] = wsum[0] + wsum[1] + wsum[2] + wsum[3];
    if (tid < Cn) {
        float a0 = 0.f, a1 = 0.f;
        if (active) {
            const float* cx = context + (b * Sn + ch * SCH) * Cn + tid;
#pragma unroll 4
            for (int sl = 0; sl < SCH; sl += 2) {
                a0 = fmaf(p[sl], cx[sl * Cn], a0);
                a1 = fmaf(p[sl + 1], cx[(sl + 1) * Cn], a1);
            }
        }
        // layout [ch][c][b]: coalesced consumption in k_lstm
        g_pctx[(ch * Cn + tid) * Bn + b] = a0 + a1;
    }
}

// ---------------- LSTM cell (one step) -----------------------------------
// grid = Hn blocks (one j each), 128 threads = 32 b x 4 gates
__global__ void __launch_bounds__(128) k_lstm(const float* __restrict__ Wih,
                                              const float* __restrict__ Whh,
                                              const float* __restrict__ bih,
                                              const float* __restrict__ bhh,
                                              int t) {
    __shared__ float ctxT[Cn][32];
    __shared__ float hsh[Hn][32];
    __shared__ float inv[32];
    __shared__ float gsh[4][32];

    int tid = threadIdx.x;
    int b = tid & 31, gate = tid >> 5;
    int j = blockIdx.x;

    if (tid < 32) {
        float s = g_psum[tid * NCH + 0] + g_psum[tid * NCH + 1] +
                  g_psum[tid * NCH + 2] + g_psum[tid * NCH + 3];
        inv[tid] = __fdividef(1.f, s);
    }
    __syncthreads();
    // coalesced: lane index == b == fastest axis of g_pctx / g_HT
    for (int idx = tid; idx < Cn * 32; idx += 128) {
        int c = idx >> 5, bb = idx & 31;
        float a = g_pctx[(0 * Cn + c) * Bn + bb] + g_pctx[(1 * Cn + c) * Bn + bb] +
                  g_pctx[(2 * Cn + c) * Bn + bb] + g_pctx[(3 * Cn + c) * Bn + bb];
        ctxT[c][bb] = a * inv[bb];
    }
    for (int idx = tid; idx < Hn * 32; idx += 128) {
        int jj = idx >> 5, bb = idx & 31;
        hsh[jj][bb] = (t == 0) ? 0.f : g_HT[((t - 1) * Hn + jj) * Bn + bb];
    }
    __syncthreads();

    const float* wi = Wih + (gate * Hn + j) * ICn;
    const float* wh = Whh + (gate * Hn + j) * Hn;
    // 4 accumulators: break the 636-FMA RAW chain
    float a0 = bih[gate * Hn + j] + bhh[gate * Hn + j];
    float a1 = 0.f, a2 = 0.f, a3 = 0.f;

    const float* xp = g_xT + t * In * Bn + b;
#pragma unroll 5
    for (int k = 0; k < In; k += 4) {
        float4 w4 = *(const float4*)(wi + k);
        a0 = fmaf(w4.x, xp[(k + 0) * Bn], a0);
        a1 = fmaf(w4.y, xp[(k + 1) * Bn], a1);
        a2 = fmaf(w4.z, xp[(k + 2) * Bn], a2);
        a3 = fmaf(w4.w, xp[(k + 3) * Bn], a3);
    }
#pragma unroll 6
    for (int k = 0; k < Cn; k += 4) {
        float4 w4 = *(const float4*)(wi + In + k);
        a0 = fmaf(w4.x, ctxT[k + 0][b], a0);
        a1 = fmaf(w4.y, ctxT[k + 1][b], a1);
        a2 = fmaf(w4.z, ctxT[k + 2][b], a2);
        a3 = fmaf(w4.w, ctxT[k + 3][b], a3);
    }
#pragma unroll 6
    for (int k = 0; k < Hn; k += 4) {
        float4 w4 = *(const float4*)(wh + k);
        a0 = fmaf(w4.x, hsh[k + 0][b], a0);
        a1 = fmaf(w4.y, hsh[k + 1][b], a1);
        a2 = fmaf(w4.z, hsh[k + 2][b], a2);
        a3 = fmaf(w4.w, hsh[k + 3][b], a3);
    }
    gsh[gate][b] = (a0 + a1) + (a2 + a3);
    __syncthreads();

    if (gate == 0) {
        float gi = gsh[0][b], gf = gsh[1][b], gg = gsh[2][b], go = gsh[3][b];
        float cold = g_c[b * Hn + j];
        float cn = fsig(gf) * cold + fsig(gi) * ftanh(gg);
        float hn = fsig(go) * ftanh(cn);
        g_c[b * Hn + j] = cn;
        g_Hall[(b * Tn + t) * Hn + j] = hn;          // row-major for decode
        g_HT[(t * Hn + j) * Bn + b] = hn;            // [t][j][b] for recurrence
    }
}

// ---------------- decode GEMM: out[m][v] = Hall[m][:] . Wdec[v][:] -------
// M=2048, N=50257, K=168. Each block: one 128-wide N tile (Bs) reused
// across TWO 128-row M tiles. f32x2 packed FFMA accumulators.
// NOTE: epilogue uses 32-bit stores ONLY — Vn is odd, so odd output rows
// are 4B-aligned; STG.64 there traps (misaligned address).
#define DPAD 132  // row stride (floats): 16B aligned, 132%32=4 -> k-varying banks
#define DEC_SMEM (2 * Hn * DPAD * 4)

__global__ void __launch_bounds__(256, 1)
k_decode(const float* __restrict__ Wdec, float* __restrict__ out) {
    extern __shared__ float sm[];
    float* As = sm;               // [168][132]
    float* Bs = sm + Hn * DPAD;   // [168][132]
    const int nb = blockIdx.x * 128;
    const int tid = threadIdx.x;

    // load Wdec tile once (reused for both m-halves)
    for (int idx = tid; idx < 128 * 42; idx += 256) {
        int nl = idx / 42, kq = (idx % 42) * 4;
        int vv = nb + nl;
        float4 w = make_float4(0.f, 0.f, 0.f, 0.f);
        if (vv < Vn) w = *(const float4*)(Wdec + vv * Hn + kq);
        Bs[(kq + 0) * DPAD + nl] = w.x;
        Bs[(kq + 1) * DPAD + nl] = w.y;
        Bs[(kq + 2) * DPAD + nl] = w.z;
        Bs[(kq + 3) * DPAD + nl] = w.w;
    }

    const int tx = tid & 15, ty = tid >> 4;
    const int mo = ty * 8, no = tx * 8;

    for (int mi = 0; mi < 2; ++mi) {
        const int mb = blockIdx.y * 256 + mi * 128;
        __syncthreads();  // protect As from previous iteration's readers
        for (int idx = tid; idx < 128 * 42; idx += 256) {
            int ml = idx / 42, kq = (idx % 42) * 4;
            float4 v = *(const float4*)(g_Hall + (mb + ml) * Hn + kq);
            As[(kq + 0) * DPAD + ml] = v.x;
            As[(kq + 1) * DPAD + ml] = v.y;
            As[(kq + 2) * DPAD + ml] = v.z;
            As[(kq + 3) * DPAD + ml] = v.w;
        }
        __syncthreads();

        unsigned long long acc[8][4];
#pragma unroll
        for (int i = 0; i < 8; ++i)
#pragma unroll
            for (int jj = 0; jj < 4; ++jj) acc[i][jj] = 0ULL;

#pragma unroll 4
        for (int k = 0; k < Hn; ++k) {
            const float* ar = As + k * DPAD + mo;
            float4 a0 = *(const float4*)(ar);
            float4 a1 = *(const float4*)(ar + 4);
            unsigned long long da[8];
            da[0] = dup2(a0.x); da[1] = dup2(a0.y); da[2] = dup2(a0.z); da[3] = dup2(a0.w);
            da[4] = dup2(a1.x); da[5] = dup2(a1.y); da[6] = dup2(a1.z); da[7] = dup2(a1.w);
            const ulonglong2* br = (const ulonglong2*)(Bs + k * DPAD + no);
            ulonglong2 q0 = br[0], q1 = br[1];
            unsigned long long bb[4] = {q0.x, q0.y, q1.x, q1.y};
#pragma unroll
            for (int i = 0; i < 8; ++i)
#pragma unroll
                for (int jj = 0; jj < 4; ++jj)
                    acc[i][jj] = ffma2(da[i], bb[jj], acc[i][jj]);
        }

#pragma unroll
        for (int i = 0; i < 8; ++i) {
            int row = mb + mo + i;
            float* orow = out + (size_t)row * Vn + nb + no;
#pragma unroll
            for (int jj = 0; jj < 4; ++jj) {
                float lo, hi;
                unpack2(acc[i][jj], lo, hi);
                int col = nb + no + 2 * jj;
                if (col < Vn) orow[2 * jj] = lo;
                if (col + 1 < Vn) orow[2 * jj + 1] = hi;
            }
        }
    }
}

// ---------------- launch ---------------------------------------------------
extern "C" void kernel_launch(void* const* d_in, const int* in_sizes, int n_in,
                              void* d_out, int out_size) {
    const float* x       = (const float*)d_in[0];
    const float* context = (const float*)d_in[1];
    const int*   clen    = (const int*)  d_in[2];
    const float* Wih     = (const float*)d_in[3];
    const float* Whh     = (const float*)d_in[4];
    const float* bih     = (const float*)d_in[5];
    const float* bhh     = (const float*)d_in[6];
    const float* aWx     = (const float*)d_in[7];
    const float* aWs     = (const float*)d_in[8];
    const float* ab      = (const float*)d_in[9];
    const float* av      = (const float*)d_in[10];
    const float* Wdec    = (const float*)d_in[11];
    float* out = (float*)d_out;

    k_xT<<<(Tn * In * Bn + 255) / 256, 256>>>(x);
    k_seqproj<<<dim3(Sn / 64, Bn), 256>>>(context, aWs);

    for (int t = 0; t < Tn; ++t) {
        k_attn<<<dim3(NCH, Bn), 256>>>(context, clen, aWx, ab, av, t);
        k_lstm<<<Hn, 128>>>(Wih, Whh, bih, bhh, t);
    }

    cudaFuncSetAttribute(k_decode, cudaFuncAttributeMaxDynamicSharedMemorySize, DEC_SMEM);
    k_decode<<<dim3((Vn + 127) / 128, (Bn * Tn) / 256), 256, DEC_SMEM>>>(Wdec, out);
}

// round 16
// speedup vs baseline: 1.0525x; 1.0525x over previous
#include <cuda_runtime.h>
#include <math.h>

#define Bn 32
#define Tn 64
#define In 300
#define Hn 168
#define Cn 168
#define Sn 512
#define Vn 50257
#define ICn (In + Cn)      // 468
#define NCH 8
#define SCH (Sn / NCH)     // 64
#define HQ 42              // h-quarter for attention tanh phase

// ---------------- device scratch (static, no allocation) ----------------
__device__ __align__(16) float g_spT[Bn * Hn * Sn];   // seq_proj transposed [b][h][s]
__device__ __align__(16) float g_xT[Tn * In * Bn];    // x transposed [t][k][b]
__device__ __align__(16) float g_c[Bn * Hn];          // LSTM cell state [b][j]
__device__ __align__(16) float g_psum[Bn * NCH];      // softmax partial sums
__device__ __align__(16) float g_pctx[NCH * Cn * Bn]; // ctx partials [ch][c][b]
__device__ __align__(16) float g_Hall[Bn * Tn * Hn];  // hidden states row-major
__device__ __align__(16) float g_HT[Tn * Hn * Bn];    // hidden states [t][j][b]
__device__ __align__(16) float g_z[Bn * Hn];          // z = att_b + h@att_Wx, [b][h]

// ---------------- fast-accurate activations (MUFU EX2/RCP, ~1e-6 rel) ----
__device__ __forceinline__ float fsig(float x) {
    return __fdividef(1.f, 1.f + __expf(-x));
}
__device__ __forceinline__ float ftanh(float x) {
    return 1.f - __fdividef(2.f, __expf(2.f * x) + 1.f);
}

// ---------------- f32x2 packed math helpers -----------------------------
__device__ __forceinline__ unsigned long long dup2(float a) {
    unsigned long long d;
    asm("mov.b64 %0, {%1, %1};" : "=l"(d) : "f"(a));
    return d;
}
__device__ __forceinline__ unsigned long long ffma2(unsigned long long a,
                                                    unsigned long long b,
                                                    unsigned long long c) {
    unsigned long long d;
    asm("fma.rn.f32x2 %0, %1, %2, %3;" : "=l"(d) : "l"(a), "l"(b), "l"(c));
    return d;
}
__device__ __forceinline__ void unpack2(unsigned long long v, float& lo, float& hi) {
    asm("mov.b64 {%0, %1}, %2;" : "=f"(lo), "=f"(hi) : "l"(v));
}

// ---------------- transpose x -> xT[t][k][b]; also zero cell state -------
__global__ void __launch_bounds__(256) k_xT(const float* __restrict__ x) {
    int i = blockIdx.x * blockDim.x + threadIdx.x;
    if (i < Tn * In * Bn) {
        int b = i % Bn;
        int k = (i / Bn) % In;
        int t = i / (Bn * In);
        g_xT[i] = x[(b * Tn + t) * In + k];
    }
    if (i < Bn * Hn) g_c[i] = 0.f;
}

// ---------------- seq_proj: spT[b][h][s] = sum_c context[b][s][c]*Ws[c][h]
__global__ void __launch_bounds__(256) k_seqproj(const float* __restrict__ context,
                                                 const float* __restrict__ att_Ws) {
    __shared__ float cs[64 * 169];
    int b = blockIdx.y;
    int s0 = blockIdx.x * 64;
    for (int idx = threadIdx.x; idx < 64 * Cn; idx += 256) {
        int sl = idx / Cn, c = idx % Cn;
        cs[sl * 169 + c] = context[(b * Sn + s0 + sl) * Cn + c];
    }
    __syncthreads();
    for (int oi = threadIdx.x; oi < Hn * 64; oi += 256) {
        int h = oi / 64, sl = oi % 64;
        float a0 = 0.f, a1 = 0.f;
        const float* wp = att_Ws + h;
        const float* cp = cs + sl * 169;
#pragma unroll 4
        for (int c = 0; c < Cn; c += 2) {
            a0 = fmaf(cp[c], wp[c * Hn], a0);
            a1 = fmaf(cp[c + 1], wp[(c + 1) * Hn], a1);
        }
        g_spT[(b * Hn + h) * Sn + s0 + sl] = a0 + a1;
    }
}

// ---------------- z projection: z[b][h] = att_b[h] + h_{t-1} @ att_Wx ----
// grid=32 (b), 384 threads: 2-way j-split, 4 accumulators per half.
__global__ void __launch_bounds__(384) k_z(const float* __restrict__ att_Wx,
                                           const float* __restrict__ att_b,
                                           int t) {
    __shared__ float hs[Hn], part[2][Hn];
    int b = blockIdx.x;
    int tid = threadIdx.x;
    if (tid < Hn)
        hs[tid] = (t == 0) ? 0.f : g_Hall[(b * Tn + (t - 1)) * Hn + tid];
    __syncthreads();
    if (tid < 2 * Hn) {
        int half = (tid >= Hn);
        int h = tid - half * Hn;
        int j0 = half * 84;
        float a0 = 0.f, a1 = 0.f, a2 = 0.f, a3 = 0.f;
#pragma unroll 4
        for (int j = j0; j < j0 + 84; j += 4) {
            a0 = fmaf(hs[j + 0], att_Wx[(j + 0) * Hn + h], a0);
            a1 = fmaf(hs[j + 1], att_Wx[(j + 1) * Hn + h], a1);
            a2 = fmaf(hs[j + 2], att_Wx[(j + 2) * Hn + h], a2);
            a3 = fmaf(hs[j + 3], att_Wx[(j + 3) * Hn + h], a3);
        }
        part[half][h] = (a0 + a1) + (a2 + a3);
    }
    __syncthreads();
    if (tid < Hn) g_z[b * Hn + tid] = att_b[tid] + part[0][tid] + part[1][tid];
}

// ---------------- attention (one step): energies + partial softmax + ctx --
// grid=(NCH=8, Bn), 256 threads = 64 s x 4 h-quarters.
__global__ void __launch_bounds__(256) k_attn(const float* __restrict__ context,
                                              const int* __restrict__ clen,
                                              const float* __restrict__ att_v,
                                              int t) {
    __shared__ float zsh[Hn], av[Hn], p[SCH], pe4[4][SCH], wsum[2];
    int b = blockIdx.y, ch = blockIdx.x;
    int tid = threadIdx.x;

    int len = clen[b];
    bool active = (ch * SCH) < len;   // block-uniform

    if (tid < Hn) {
        zsh[tid] = g_z[b * Hn + tid];
        av[tid] = att_v[tid];
    }
    __syncthreads();

    if (active) {
        int sl = tid & (SCH - 1);
        int hq = tid >> 6;            // 0..3
        int s = ch * SCH + sl;
        float e = 0.f;
        if (s < len) {
            const float* sp = g_spT + b * Hn * Sn + s;
            int h0 = hq * HQ;
#pragma unroll 4
            for (int h = h0; h < h0 + HQ; ++h) {
                float u = zsh[h] + sp[h * Sn];
                e = fmaf(av[h], ftanh(u), e);
            }
        }
        pe4[hq][sl] = e;
        __syncthreads();
    }

    if (tid < SCH) {
        int s = ch * SCH + tid;
        // |e| <= sum|att_v| ~ 6.7 -> exp never overflows; masked -> 0
        float pe = (active && s < len)
                       ? __expf(pe4[0][tid] + pe4[1][tid] + pe4[2][tid] + pe4[3][tid])
                       : 0.f;
        p[tid] = pe;
        float r = pe;
#pragma unroll
        for (int off = 16; off; off >>= 1) r += __shfl_down_sync(0xffffffffu, r, off);
        if ((tid & 31) == 0) wsum[tid >> 5] = r;
    }
    __syncthreads();
    if (tid == 0) g_psum[b * NCH + ch] = wsum[0] + wsum[1];
    if (tid < Cn) {
        float a0 = 0.f, a1 = 0.f;
        if (active) {
            const float* cx = context + (b * Sn + ch * SCH) * Cn + tid;
#pragma unroll 4
            for (int sl = 0; sl < SCH; sl += 2) {
                a0 = fmaf(p[sl], cx[sl * Cn], a0);
                a1 = fmaf(p[sl + 1], cx[(sl + 1) * Cn], a1);
            }
        }
        g_pctx[(ch * Cn + tid) * Bn + b] = a0 + a1;
    }
}

// ---------------- LSTM cell (one step), fully smem-staged -----------------
// grid = Hn blocks (one j each), 128 threads = 32 b x 4 gates.
// ALL operands staged to smem with wide parallel loads (fix for the measured
// MLP~1 global-latency serialization: 27.5us -> ~3us predicted).
// dynamic smem layout (floats):
//   xs[In*32] | ctxT[Hn*32] | hsh[Hn*32] | wiF[4*ICn] | whF[4*Hn] | inv[32] | gsh[128]
#define L_XS   0
#define L_CTX  (In * 32)                    // 9600
#define L_HSH  (L_CTX + Hn * 32)            // 14976
#define L_WI   (L_HSH + Hn * 32)            // 20352
#define L_WH   (L_WI + 4 * ICn)             // 22224
#define L_INV  (L_WH + 4 * Hn)              // 22896
#define L_GSH  (L_INV + 32)                 // 22928
#define LSTM_SMEM ((L_GSH + 128) * 4)       // 92224 B

__global__ void __launch_bounds__(128, 1) k_lstm(const float* __restrict__ Wih,
                                                 const float* __restrict__ Whh,
                                                 const float* __restrict__ bih,
                                                 const float* __restrict__ bhh,
                                                 int t) {
    extern __shared__ float sm[];
    float* xs = sm + L_XS;
    float* ctxT = sm + L_CTX;
    float* hsh = sm + L_HSH;
    float* wiF = sm + L_WI;
    float* whF = sm + L_WH;
    float* inv = sm + L_INV;
    float* gsh = sm + L_GSH;

    int tid = threadIdx.x;
    int b = tid & 31, gate = tid >> 5;
    int j = blockIdx.x;

    if (tid < 32) {
        float s = 0.f;
#pragma unroll
        for (int ch = 0; ch < NCH; ++ch) s += g_psum[tid * NCH + ch];
        inv[tid] = __fdividef(1.f, s);
    }
    __syncthreads();

    // ---- stage all operands with wide parallel (high-MLP) loads ----
    {   // x_t slice: 2400 float4, linear copy
        const float4* gx4 = (const float4*)(g_xT + t * In * Bn);
        float4* xs4 = (float4*)xs;
        for (int idx = tid; idx < In * 32 / 4; idx += 128) xs4[idx] = gx4[idx];
    }
    {   // combined + scaled ctx: 1344 float4
        float4* c4 = (float4*)ctxT;
        const float4* iv4 = (const float4*)inv;
        for (int idx = tid; idx < Hn * 8; idx += 128) {
            int c = idx >> 3, q = idx & 7;
            float4 a = make_float4(0.f, 0.f, 0.f, 0.f);
#pragma unroll
            for (int ch = 0; ch < NCH; ++ch) {
                const float4* p4 = (const float4*)(g_pctx + (ch * Cn + c) * Bn);
                float4 v = p4[q];
                a.x += v.x; a.y += v.y; a.z += v.z; a.w += v.w;
            }
            float4 iv = iv4[q];
            a.x *= iv.x; a.y *= iv.y; a.z *= iv.z; a.w *= iv.w;
            c4[idx] = a;
        }
    }
    {   // h_{t-1}: 1344 float4
        float4* h4 = (float4*)hsh;
        if (t == 0) {
            float4 z4 = make_float4(0.f, 0.f, 0.f, 0.f);
            for (int idx = tid; idx < Hn * 8; idx += 128) h4[idx] = z4;
        } else {
            const float4* g4 = (const float4*)(g_HT + (t - 1) * Hn * Bn);
            for (int idx = tid; idx < Hn * 8; idx += 128) h4[idx] = g4[idx];
        }
    }
    {   // weights: 4 Wih rows (117 f4 each) + 4 Whh rows (42 f4 each)
        float4* wi4 = (float4*)wiF;
        for (int idx = tid; idx < 4 * 117; idx += 128) {
            int row = idx / 117, kq = idx % 117;
            wi4[row * 117 + kq] = ((const float4*)(Wih + (row * Hn + j) * ICn))[kq];
        }
        float4* wh4 = (float4*)whF;
        for (int idx = tid; idx < 4 * 42; idx += 128) {
            int row = idx / 42, kq = idx % 42;
            wh4[row * 42 + kq] = ((const float4*)(Whh + (row * Hn + j) * Hn))[kq];
        }
    }
    __syncthreads();

    // ---- compute from smem: weight reads are lane-broadcast ----
    const float* wi = wiF + gate * ICn;
    const float* wh = whF + gate * Hn;
    float a0 = bih[gate * Hn + j] + bhh[gate * Hn + j];
    float a1 = 0.f, a2 = 0.f, a3 = 0.f;

#pragma unroll 5
    for (int k = 0; k < In; k += 4) {
        float4 w4 = *(const float4*)(wi + k);
        a0 = fmaf(w4.x, xs[(k + 0) * 32 + b], a0);
        a1 = fmaf(w4.y, xs[(k + 1) * 32 + b], a1);
        a2 = fmaf(w4.z, xs[(k + 2) * 32 + b], a2);
        a3 = fmaf(w4.w, xs[(k + 3) * 32 + b], a3);
    }
#pragma unroll 6
    for (int k = 0; k < Cn; k += 4) {
        float4 w4 = *(const float4*)(wi + In + k);
        a0 = fmaf(w4.x, ctxT[(k + 0) * 32 + b], a0);
        a1 = fmaf(w4.y, ctxT[(k + 1) * 32 + b], a1);
        a2 = fmaf(w4.z, ctxT[(k + 2) * 32 + b], a2);
        a3 = fmaf(w4.w, ctxT[(k + 3) * 32 + b], a3);
    }
#pragma unroll 6
    for (int k = 0; k < Hn; k += 4) {
        float4 w4 = *(const float4*)(wh + k);
        a0 = fmaf(w4.x, hsh[(k + 0) * 32 + b], a0);
        a1 = fmaf(w4.y, hsh[(k + 1) * 32 + b], a1);
        a2 = fmaf(w4.z, hsh[(k + 2) * 32 + b], a2);
        a3 = fmaf(w4.w, hsh[(k + 3) * 32 + b], a3);
    }
    gsh[gate * 32 + b] = (a0 + a1) + (a2 + a3);
    __syncthreads();

    if (gate == 0) {
        float gi = gsh[0 * 32 + b], gf = gsh[1 * 32 + b];
        float gg = gsh[2 * 32 + b], go = gsh[3 * 32 + b];
        float cold = g_c[b * Hn + j];
        float cn = fsig(gf) * cold + fsig(gi) * ftanh(gg);
        float hn = fsig(go) * ftanh(cn);
        g_c[b * Hn + j] = cn;
        g_Hall[(b * Tn + t) * Hn + j] = hn;
        g_HT[(t * Hn + j) * Bn + b] = hn;
    }
}

// ---------------- decode GEMM: unchanged (FFMA2, 32-bit epilogue stores) --
#define DPAD 132
#define DEC_SMEM (2 * Hn * DPAD * 4)

__global__ void __launch_bounds__(256, 1)
k_decode(const float* __restrict__ Wdec, float* __restrict__ out) {
    extern __shared__ float sm[];
    float* As = sm;
    float* Bs = sm + Hn * DPAD;
    const int nb = blockIdx.x * 128;
    const int tid = threadIdx.x;

    for (int idx = tid; idx < 128 * 42; idx += 256) {
        int nl = idx / 42, kq = (idx % 42) * 4;
        int vv = nb + nl;
        float4 w = make_float4(0.f, 0.f, 0.f, 0.f);
        if (vv < Vn) w = *(const float4*)(Wdec + vv * Hn + kq);
        Bs[(kq + 0) * DPAD + nl] = w.x;
        Bs[(kq + 1) * DPAD + nl] = w.y;
        Bs[(kq + 2) * DPAD + nl] = w.z;
        Bs[(kq + 3) * DPAD + nl] = w.w;
    }

    const int tx = tid & 15, ty = tid >> 4;
    const int mo = ty * 8, no = tx * 8;

    for (int mi = 0; mi < 2; ++mi) {
        const int mb = blockIdx.y * 256 + mi * 128;
        __syncthreads();
        for (int idx = tid; idx < 128 * 42; idx += 256) {
            int ml = idx / 42, kq = (idx % 42) * 4;
            float4 v = *(const float4*)(g_Hall + (mb + ml) * Hn + kq);
            As[(kq + 0) * DPAD + ml] = v.x;
            As[(kq + 1) * DPAD + ml] = v.y;
            As[(kq + 2) * DPAD + ml] = v.z;
            As[(kq + 3) * DPAD + ml] = v.w;
        }
        __syncthreads();

        unsigned long long acc[8][4];
#pragma unroll
        for (int i = 0; i < 8; ++i)
#pragma unroll
            for (int jj = 0; jj < 4; ++jj) acc[i][jj] = 0ULL;

#pragma unroll 4
        for (int k = 0; k < Hn; ++k) {
            const float* ar = As + k * DPAD + mo;
            float4 a0 = *(const float4*)(ar);
            float4 a1 = *(const float4*)(ar + 4);
            unsigned long long da[8];
            da[0] = dup2(a0.x); da[1] = dup2(a0.y); da[2] = dup2(a0.z); da[3] = dup2(a0.w);
            da[4] = dup2(a1.x); da[5] = dup2(a1.y); da[6] = dup2(a1.z); da[7] = dup2(a1.w);
            const ulonglong2* br = (const ulonglong2*)(Bs + k * DPAD + no);
            ulonglong2 q0 = br[0], q1 = br[1];
            unsigned long long bb[4] = {q0.x, q0.y, q1.x, q1.y};
#pragma unroll
            for (int i = 0; i < 8; ++i)
#pragma unroll
                for (int jj = 0; jj < 4; ++jj)
                    acc[i][jj] = ffma2(da[i], bb[jj], acc[i][jj]);
        }

#pragma unroll
        for (int i = 0; i < 8; ++i) {
            int row = mb + mo + i;
            float* orow = out + (size_t)row * Vn + nb + no;
#pragma unroll
            for (int jj = 0; jj < 4; ++jj) {
                float lo, hi;
                unpack2(acc[i][jj], lo, hi);
                int col = nb + no + 2 * jj;
                if (col < Vn) orow[2 * jj] = lo;
                if (col + 1 < Vn) orow[2 * jj + 1] = hi;
            }
        }
    }
}

// ---------------- launch ---------------------------------------------------
extern "C" void kernel_launch(void* const* d_in, const int* in_sizes, int n_in,
                              void* d_out, int out_size) {
    const float* x       = (const float*)d_in[0];
    const float* context = (const float*)d_in[1];
    const int*   clen    = (const int*)  d_in[2];
    const float* Wih     = (const float*)d_in[3];
    const float* Whh     = (const float*)d_in[4];
    const float* bih     = (const float*)d_in[5];
    const float* bhh     = (const float*)d_in[6];
    const float* aWx     = (const float*)d_in[7];
    const float* aWs     = (const float*)d_in[8];
    const float* ab      = (const float*)d_in[9];
    const float* av      = (const float*)d_in[10];
    const float* Wdec    = (const float*)d_in[11];
    float* out = (float*)d_out;

    cudaFuncSetAttribute(k_lstm, cudaFuncAttributeMaxDynamicSharedMemorySize, LSTM_SMEM);
    cudaFuncSetAttribute(k_decode, cudaFuncAttributeMaxDynamicSharedMemorySize, DEC_SMEM);

    k_xT<<<(Tn * In * Bn + 255) / 256, 256>>>(x);
    k_seqproj<<<dim3(Sn / 64, Bn), 256>>>(context, aWs);

    for (int t = 0; t < Tn; ++t) {
        k_z<<<Bn, 384>>>(aWx, ab, t);
        k_attn<<<dim3(NCH, Bn), 256>>>(context, clen, av, t);
        k_lstm<<<Hn, 128, LSTM_SMEM>>>(Wih, Whh, bih, bhh, t);
    }

    k_decode<<<dim3((Vn + 127) / 128, (Bn * Tn) / 256), 256, DEC_SMEM>>>(Wdec, out);
}